// round 1
// baseline (speedup 1.0000x reference)
#include <cuda_runtime.h>
#include <math.h>

// Problem constants (shapes fixed by setup_inputs)
#define BATCH 64
#define CDIM  768
#define TWOC  1536
#define NTOK  1025
#define HW    1024      // 32x32 spatial
#define NWC   8
#define RREG  64        // regions
#define SREG  16        // positions per region
#define NHEAD 12
#define HD    64
#define TOPKN 32

// ---------------- scratch (static device globals; no allocations) ----------
static __device__ float g_kv[(size_t)BATCH * TWOC * HW];   // 402.7 MB: k rows [0,768), v rows [768,1536)
static __device__ float g_q [BATCH * CDIM];
static __device__ float g_kr[(size_t)BATCH * CDIM * RREG];
static __device__ int   g_sel[BATCH * TOPKN];
static __device__ float g_o [BATCH * CDIM];

// ---------------- K1: q = x[:,0] @ Wq.T + bq  (warp per output) ------------
__global__ void k_qproj(const float* __restrict__ x, const float* __restrict__ Wq,
                        const float* __restrict__ bq) {
    int b = blockIdx.x;
    __shared__ float xs[CDIM];
    int tid = threadIdx.x;
    for (int c = tid; c < CDIM; c += 256) xs[c] = x[(size_t)b * NTOK * CDIM + c];
    __syncthreads();
    int w = tid >> 5, lane = tid & 31;
    int j = blockIdx.y * 8 + w;
    float s = 0.f;
    const float* wr = Wq + (size_t)j * CDIM;
    for (int c = lane; c < CDIM; c += 32) s += xs[c] * wr[c];
    #pragma unroll
    for (int off = 16; off; off >>= 1) s += __shfl_down_sync(0xffffffffu, s, off);
    if (lane == 0) g_q[b * CDIM + j] = s + bq[j];
}

// ---------------- K2: kv[b] = Wkv(1536x768) @ Xb(768x1024) + bkv -----------
// Tiled fp32 GEMM: BM=128, BN=64, BK=16, 256 threads, 8x4 per-thread microtile
#define BM 128
#define BN 64
#define BK 16
#define AS_LD 132   // padded (16B-aligned rows: 132*4=528 bytes)
#define BS_LD 68

__global__ __launch_bounds__(256) void k_gemm_kv(const float* __restrict__ x,
                                                 const float* __restrict__ Wkv,
                                                 const float* __restrict__ bkv) {
    int b  = blockIdx.z;
    int m0 = blockIdx.y * BM;
    int n0 = blockIdx.x * BN;
    const float* A  = Wkv;                                   // 1536 x 768 row-major
    const float* Bx = x + (size_t)b * NTOK * CDIM + CDIM;    // 768 x 1024 row-major view

    __shared__ float As[BK * AS_LD];
    __shared__ float Bs[BK * BS_LD];

    int tid = threadIdx.x;
    int tx = tid & 15, ty = tid >> 4;
    float acc[8][4] = {};

    for (int k0 = 0; k0 < CDIM; k0 += BK) {
        // A tile: 128x16 = 512 float4, 2 per thread; store transposed As[k][m]
        #pragma unroll
        for (int i = 0; i < 2; i++) {
            int f  = tid + i * 256;
            int m  = f >> 2;
            int kq = (f & 3) * 4;
            float4 v = *(const float4*)&A[(size_t)(m0 + m) * CDIM + k0 + kq];
            As[(kq + 0) * AS_LD + m] = v.x;
            As[(kq + 1) * AS_LD + m] = v.y;
            As[(kq + 2) * AS_LD + m] = v.z;
            As[(kq + 3) * AS_LD + m] = v.w;
        }
        // B tile: 16x64 = 256 float4, 1 per thread
        {
            int k = tid >> 4, n4 = (tid & 15) * 4;
            float4 v = *(const float4*)&Bx[(size_t)(k0 + k) * HW + n0 + n4];
            *(float4*)&Bs[k * BS_LD + n4] = v;
        }
        __syncthreads();
        #pragma unroll
        for (int k = 0; k < BK; k++) {
            float4 a0 = *(const float4*)&As[k * AS_LD + ty * 8];
            float4 a1 = *(const float4*)&As[k * AS_LD + ty * 8 + 4];
            float4 bb = *(const float4*)&Bs[k * BS_LD + tx * 4];
            float av[8] = {a0.x, a0.y, a0.z, a0.w, a1.x, a1.y, a1.z, a1.w};
            float bv[4] = {bb.x, bb.y, bb.z, bb.w};
            #pragma unroll
            for (int i = 0; i < 8; i++)
                #pragma unroll
                for (int j = 0; j < 4; j++)
                    acc[i][j] += av[i] * bv[j];
        }
        __syncthreads();
    }
    #pragma unroll
    for (int i = 0; i < 8; i++) {
        int row = m0 + ty * 8 + i;
        float bias = bkv[row];
        float4 v = make_float4(acc[i][0] + bias, acc[i][1] + bias,
                               acc[i][2] + bias, acc[i][3] + bias);
        *(float4*)&g_kv[((size_t)b * TWOC + row) * HW + n0 + tx * 4] = v;
    }
}

// ---------------- K3: region max-pool of k -> k_r (B,C,64) -----------------
__global__ void k_pool() {
    int b   = blockIdx.x;
    int lin = blockIdx.y * 256 + threadIdx.x;   // < 768*64
    int c = lin >> 6, r = lin & 63;
    int h0 = (r >> 3) * 4, w0 = (r & 7) * 4;
    const float* base = &g_kv[((size_t)b * TWOC + c) * HW + h0 * 32 + w0];
    float m = -1e30f;
    #pragma unroll
    for (int dh = 0; dh < 4; dh++) {
        float4 v = *(const float4*)&base[dh * 32];
        m = fmaxf(m, fmaxf(fmaxf(v.x, v.y), fmaxf(v.z, v.w)));
    }
    g_kr[((size_t)b * CDIM + c) * RREG + r] = m;
}

// ---------------- K4: routing scores + top-32 (rank counting) --------------
__global__ void k_route() {
    int b = blockIdx.x, tid = threadIdx.x;
    __shared__ float qs[CDIM];
    __shared__ float part[256];
    __shared__ float a[RREG];
    for (int c = tid; c < CDIM; c += 256) qs[c] = g_q[b * CDIM + c];
    __syncthreads();
    int r = tid & 63, seg = tid >> 6;   // 4 segments of 192 channels
    float s = 0.f;
    int c0 = seg * 192;
    for (int c = c0; c < c0 + 192; c++)
        s += qs[c] * g_kr[((size_t)b * CDIM + c) * RREG + r];
    part[tid] = s;
    __syncthreads();
    if (tid < RREG) a[tid] = part[tid] + part[tid + 64] + part[tid + 128] + part[tid + 192];
    __syncthreads();
    if (tid < RREG) {
        float my = a[tid];
        int rank = 0;
        #pragma unroll 8
        for (int r2 = 0; r2 < RREG; r2++) {
            float v = a[r2];
            rank += (v > my) || (v == my && r2 < tid);
        }
        if (rank < TOPKN) g_sel[b * TOPKN + rank] = tid;
    }
}

// ---------------- K5: gathered single-query attention per (b, head) --------
__global__ __launch_bounds__(128) void k_attn() {
    int b = blockIdx.x, h = blockIdx.y;
    int tid = threadIdx.x;
    __shared__ float qsh[HD];
    __shared__ float kt[HD * 17];
    __shared__ float vt[HD * 17];
    __shared__ float lg[SREG];
    __shared__ float pr[SREG];
    __shared__ float s_alpha, s_l, s_m;

    const float SCALE = 0.036084391824351615f;  // 768^-0.5
    int ch0 = h * HD;
    if (tid < HD) qsh[tid] = g_q[b * CDIM + ch0 + tid];
    if (tid == 0) { s_m = -1e30f; s_l = 0.f; s_alpha = 0.f; }
    float o_d = 0.f;
    __syncthreads();

    size_t kvb = (size_t)b * TWOC * HW;
    int d  = tid >> 1;
    int p0 = (tid & 1) * 2;

    for (int i = 0; i < TOPKN; i++) {
        int reg = g_sel[b * TOPKN + i];
        int pbase = ((reg >> 3) * 4) * 32 + (reg & 7) * 4;
        // stage K and V tiles (64 x 16) for this region
        {
            const float* sk = &g_kv[kvb + (size_t)(ch0 + d) * HW + pbase];
            float4 v0 = *(const float4*)&sk[p0 * 32];
            float4 v1 = *(const float4*)&sk[(p0 + 1) * 32];
            float* dk = &kt[d * 17 + p0 * 4];
            dk[0] = v0.x; dk[1] = v0.y; dk[2] = v0.z; dk[3] = v0.w;
            dk[4] = v1.x; dk[5] = v1.y; dk[6] = v1.z; dk[7] = v1.w;
            const float* sv = &g_kv[kvb + (size_t)(CDIM + ch0 + d) * HW + pbase];
            float4 u0 = *(const float4*)&sv[p0 * 32];
            float4 u1 = *(const float4*)&sv[(p0 + 1) * 32];
            float* dv = &vt[d * 17 + p0 * 4];
            dv[0] = u0.x; dv[1] = u0.y; dv[2] = u0.z; dv[3] = u0.w;
            dv[4] = u1.x; dv[5] = u1.y; dv[6] = u1.z; dv[7] = u1.w;
        }
        __syncthreads();
        if (tid < SREG) {
            float s = 0.f;
            #pragma unroll 16
            for (int dd = 0; dd < HD; dd++) s += qsh[dd] * kt[dd * 17 + tid];
            lg[tid] = s * SCALE;
        }
        __syncthreads();
        if (tid == 0) {
            float nm = s_m;
            #pragma unroll
            for (int s2 = 0; s2 < SREG; s2++) nm = fmaxf(nm, lg[s2]);
            float al = expf(s_m - nm);
            float su = 0.f;
            #pragma unroll
            for (int s2 = 0; s2 < SREG; s2++) { float p = expf(lg[s2] - nm); pr[s2] = p; su += p; }
            s_l = s_l * al + su;
            s_m = nm;
            s_alpha = al;
        }
        __syncthreads();
        if (tid < HD) {
            float acc = 0.f;
            #pragma unroll
            for (int s2 = 0; s2 < SREG; s2++) acc += pr[s2] * vt[tid * 17 + s2];
            o_d = o_d * s_alpha + acc;
        }
        __syncthreads();
    }
    if (tid < HD) g_o[b * CDIM + ch0 + tid] = o_d / s_l;
}

// ---------------- K6: out = o @ Wo.T (+ bo) --------------------------------
__global__ void k_outproj(float* __restrict__ out, const float* __restrict__ Wo,
                          const float* __restrict__ bo, int out_cols, int bo_n) {
    int b = blockIdx.x;
    __shared__ float osh[CDIM];
    int tid = threadIdx.x;
    for (int c = tid; c < CDIM; c += 256) osh[c] = g_o[b * CDIM + c];
    __syncthreads();
    int w = tid >> 5, lane = tid & 31;
    int j = blockIdx.y * 8 + w;
    if (j >= out_cols) return;
    float s = 0.f;
    const float* wr = Wo + (size_t)j * CDIM;
    for (int c = lane; c < CDIM; c += 32) s += osh[c] * wr[c];
    #pragma unroll
    for (int off = 16; off; off >>= 1) s += __shfl_down_sync(0xffffffffu, s, off);
    if (lane == 0) out[(size_t)b * out_cols + j] = s + (j < bo_n ? bo[j] : 0.f);
}

// ---------------- launch ---------------------------------------------------
extern "C" void kernel_launch(void* const* d_in, const int* in_sizes, int n_in,
                              void* d_out, int out_size) {
    const float* x   = (const float*)d_in[0];
    const float* Wq  = (const float*)d_in[1];
    const float* bq  = (const float*)d_in[2];
    const float* Wkv = (const float*)d_in[3];
    const float* bkv = (const float*)d_in[4];
    const float* Wo  = (const float*)d_in[5];
    const float* bo  = (const float*)d_in[6];
    float* out = (float*)d_out;

    int B = in_sizes[0] / (NTOK * CDIM);          // 64
    int out_cols = out_size / B;                  // adapt to reference output shape
    int bo_n = (n_in > 6) ? in_sizes[6] : 0;

    k_qproj  <<<dim3(B, CDIM / 8), 256>>>(x, Wq, bq);
    k_gemm_kv<<<dim3(HW / BN, TWOC / BM, B), 256>>>(x, Wkv, bkv);
    k_pool   <<<dim3(B, (CDIM * RREG) / 256), 256>>>();
    k_route  <<<dim3(B), 256>>>();
    k_attn   <<<dim3(B, NHEAD), 128>>>();
    k_outproj<<<dim3(B, (out_cols + 7) / 8), 256>>>(out, Wo, bo, out_cols, bo_n);
}

// round 3
// speedup vs baseline: 2.0369x; 2.0369x over previous
#include <cuda_runtime.h>
#include <cuda_bf16.h>
#include <math.h>
#include <stdint.h>

// Problem constants
#define BATCH 64
#define CDIM  768
#define TWOC  1536
#define NTOK  1025
#define HW    1024
#define RREG  64
#define SREG  16
#define NHEAD 12
#define HD    64
#define TOPKN 32

#define NTOT   (BATCH * HW)       // 65536 merged N
#define NCHUNK 24                 // 768 / 32
#define STAGE_BYTES 32768         // 4 tiles x 128x32 bf16 (8KB each)
#define GEMM_SMEM (3 * STAGE_BYTES)

// ---------------- scratch ----------------
static __device__ float g_kv[(size_t)BATCH * TWOC * HW];
static __device__ float g_q [BATCH * CDIM];
static __device__ float g_kr[(size_t)BATCH * CDIM * RREG];
static __device__ int   g_sel[BATCH * TOPKN];
static __device__ float g_o [BATCH * CDIM];
static __device__ __align__(128) __nv_bfloat16 g_Ahi[TWOC * CDIM];
static __device__ __align__(128) __nv_bfloat16 g_Alo[TWOC * CDIM];
static __device__ __align__(128) __nv_bfloat16 g_Bthi[(size_t)NTOT * CDIM];
static __device__ __align__(128) __nv_bfloat16 g_Btlo[(size_t)NTOT * CDIM];

// ---------------- PTX helpers (all compute_103-baseline legal) -------------
__device__ __forceinline__ uint32_t smem_u32(const void* p) {
    uint32_t a;
    asm("{ .reg .u64 t; cvta.to.shared.u64 t, %1; cvt.u32.u64 %0, t; }" : "=r"(a) : "l"(p));
    return a;
}
__device__ __forceinline__ void cp16(uint32_t dst, const void* src) {
    asm volatile("cp.async.cg.shared.global [%0], [%1], 16;" :: "r"(dst), "l"(src));
}
__device__ __forceinline__ void cp_commit() {
    asm volatile("cp.async.commit_group;");
}
__device__ __forceinline__ void cp_wait1() {
    asm volatile("cp.async.wait_group 1;");
}
__device__ __forceinline__ void ldsm4(uint32_t* r, uint32_t a) {
    asm volatile("ldmatrix.sync.aligned.m8n8.x4.shared.b16 {%0,%1,%2,%3}, [%4];"
        : "=r"(r[0]), "=r"(r[1]), "=r"(r[2]), "=r"(r[3]) : "r"(a));
}
__device__ __forceinline__ void mma16816(float* d, const uint32_t* a, const uint32_t* b) {
    asm volatile("mma.sync.aligned.m16n8k16.row.col.f32.bf16.bf16.f32 "
        "{%0,%1,%2,%3}, {%4,%5,%6,%7}, {%8,%9}, {%0,%1,%2,%3};"
        : "+f"(d[0]), "+f"(d[1]), "+f"(d[2]), "+f"(d[3])
        : "r"(a[0]), "r"(a[1]), "r"(a[2]), "r"(a[3]), "r"(b[0]), "r"(b[1]));
}

// ---------------- K0a: split Wkv -> bf16 hi/lo ----------------
__global__ void k_convA(const float* __restrict__ Wkv) {
    int i = blockIdx.x * 256 + threadIdx.x;
    if (i < TWOC * CDIM) {
        float w = Wkv[i];
        __nv_bfloat16 h = __float2bfloat16(w);
        g_Ahi[i] = h;
        g_Alo[i] = __float2bfloat16(w - __bfloat162float(h));
    }
}

// ---------------- K0b: transpose+split x_spa -> Bt[n,k] bf16 hi/lo ---------
__global__ void k_convB(const float* __restrict__ x) {
    __shared__ float t[32][33];
    int b  = blockIdx.z;
    int n0 = blockIdx.x * 32;
    int k0 = blockIdx.y * 32;
    const float* src = x + (size_t)b * NTOK * CDIM + CDIM;
    int tx = threadIdx.x, ty = threadIdx.y;
    #pragma unroll
    for (int i = ty; i < 32; i += 8)
        t[i][tx] = src[(size_t)(k0 + i) * HW + n0 + tx];
    __syncthreads();
    #pragma unroll
    for (int i = ty; i < 32; i += 8) {
        float w = t[tx][i];    // (k = k0+tx, n = n0+i)
        __nv_bfloat16 h = __float2bfloat16(w);
        size_t idx = ((size_t)b * HW + n0 + i) * CDIM + k0 + tx;
        g_Bthi[idx] = h;
        g_Btlo[idx] = __float2bfloat16(w - __bfloat162float(h));
    }
}

// ---------------- K1: q projection ----------------
__global__ void k_qproj(const float* __restrict__ x, const float* __restrict__ Wq,
                        const float* __restrict__ bq) {
    int b = blockIdx.x;
    __shared__ float xs[CDIM];
    int tid = threadIdx.x;
    for (int c = tid; c < CDIM; c += 256) xs[c] = x[(size_t)b * NTOK * CDIM + c];
    __syncthreads();
    int w = tid >> 5, lane = tid & 31;
    int j = blockIdx.y * 8 + w;
    float s = 0.f;
    const float* wr = Wq + (size_t)j * CDIM;
    for (int c = lane; c < CDIM; c += 32) s += xs[c] * wr[c];
    #pragma unroll
    for (int off = 16; off; off >>= 1) s += __shfl_down_sync(0xffffffffu, s, off);
    if (lane == 0) g_q[b * CDIM + j] = s + bq[j];
}

// ---------------- K2: HMMA split-bf16 GEMM ----------------
// D[1536,65536] = Wkv @ X. CTA: 128x128, 8 warps 64x32, 3-stage cp.async.
__global__ void __launch_bounds__(256) k_gemm_mma(const float* __restrict__ bkv) {
    extern __shared__ __align__(1024) char smem[];
    uint32_t sb = smem_u32(smem);
    int tid = threadIdx.x;
    int m0 = blockIdx.x * 128;            // 12 m-tiles (fast dim -> B reuse)
    int n0 = blockIdx.y * 128;            // 512 n-tiles

    // ---- stage loader: 4 tiles of 128x32 bf16, swizzled for ldmatrix ----
    auto load_stage = [&](uint32_t st, int kc) {
        #pragma unroll
        for (int rep = 0; rep < 2; rep++) {
            int q    = tid + rep * 256;          // 0..511
            int row  = q >> 2, quad = q & 3;
            uint32_t doff = row * 64 + ((quad ^ ((row >> 1) & 3)) << 4);
            size_t aoff = (size_t)(m0 + row) * CDIM + kc + quad * 8;
            size_t boff = (size_t)(n0 + row) * CDIM + kc + quad * 8;
            cp16(st +         doff, g_Ahi  + aoff);
            cp16(st +  8192 + doff, g_Alo  + aoff);
            cp16(st + 16384 + doff, g_Bthi + boff);
            cp16(st + 24576 + doff, g_Btlo + boff);
        }
        cp_commit();
    };

    load_stage(sb, 0);
    load_stage(sb + STAGE_BYTES, 32);

    int lane = tid & 31;
    int wid  = tid >> 5;
    int wm = wid >> 2, wn = wid & 3;

    // ldmatrix per-lane address components
    uint32_t a_base = (uint32_t)((wm * 64 + (lane & 15)) * 64);
    uint32_t swa    = ((lane & 15) >> 1) & 3;
    uint32_t akh    = lane >> 4;
    uint32_t b_row  = (uint32_t)(wn * 32 + ((lane >> 4) << 3) + (lane & 7));
    uint32_t b_base = b_row * 64;
    uint32_t swb    = ((((lane >> 4) << 3) + (lane & 7)) >> 1) & 3;
    uint32_t bkh    = (lane >> 3) & 1;

    float acc[4][4][4] = {};

    for (int c = 0; c < NCHUNK; c++) {
        cp_wait1();
        __syncthreads();
        if (c + 2 < NCHUNK) load_stage(sb + ((c + 2) % 3) * STAGE_BYTES, (c + 2) * 32);
        uint32_t st = sb + (c % 3) * STAGE_BYTES;

        #pragma unroll
        for (int ks = 0; ks < 2; ks++) {
            uint32_t qk = ks * 2;
            uint32_t aoff = a_base + (((qk + akh) ^ swa) << 4);
            uint32_t boff = b_base + (((qk + bkh) ^ swb) << 4);
            uint32_t ah[4][4], al[4][4], bb[4][2];
            #pragma unroll
            for (int mt = 0; mt < 4; mt++) ldsm4(ah[mt], st + mt * 1024 + aoff);
            ldsm4(&bb[0][0], st + 16384 + boff);
            ldsm4(&bb[2][0], st + 16384 + boff + 1024);
            #pragma unroll
            for (int mt = 0; mt < 4; mt++)
                #pragma unroll
                for (int nt = 0; nt < 4; nt++) mma16816(acc[mt][nt], ah[mt], bb[nt]);
            #pragma unroll
            for (int mt = 0; mt < 4; mt++) ldsm4(al[mt], st + 8192 + mt * 1024 + aoff);
            #pragma unroll
            for (int mt = 0; mt < 4; mt++)
                #pragma unroll
                for (int nt = 0; nt < 4; nt++) mma16816(acc[mt][nt], al[mt], bb[nt]);
            ldsm4(&bb[0][0], st + 24576 + boff);
            ldsm4(&bb[2][0], st + 24576 + boff + 1024);
            #pragma unroll
            for (int mt = 0; mt < 4; mt++)
                #pragma unroll
                for (int nt = 0; nt < 4; nt++) mma16816(acc[mt][nt], ah[mt], bb[nt]);
        }
    }

    // ---- epilogue: write g_kv with bias ----
    int b    = n0 >> 10;
    int pos0 = (n0 & 1023) + wn * 32;
    #pragma unroll
    for (int mt = 0; mt < 4; mt++) {
        int row = m0 + wm * 64 + mt * 16 + (lane >> 2);
        float bias0 = bkv[row], bias8 = bkv[row + 8];
        float* base0 = &g_kv[((size_t)b * TWOC + row) * HW + pos0];
        float* base8 = base0 + (size_t)8 * HW;
        #pragma unroll
        for (int nt = 0; nt < 4; nt++) {
            int col = nt * 8 + (lane & 3) * 2;
            float2 v0 = make_float2(acc[mt][nt][0] + bias0, acc[mt][nt][1] + bias0);
            float2 v8 = make_float2(acc[mt][nt][2] + bias8, acc[mt][nt][3] + bias8);
            *(float2*)&base0[col] = v0;
            *(float2*)&base8[col] = v8;
        }
    }
}

// ---------------- K3: region max-pool ----------------
__global__ void k_pool() {
    int b   = blockIdx.x;
    int lin = blockIdx.y * 256 + threadIdx.x;
    int c = lin >> 6, r = lin & 63;
    int h0 = (r >> 3) * 4, w0 = (r & 7) * 4;
    const float* base = &g_kv[((size_t)b * TWOC + c) * HW + h0 * 32 + w0];
    float m = -1e30f;
    #pragma unroll
    for (int dh = 0; dh < 4; dh++) {
        float4 v = *(const float4*)&base[dh * 32];
        m = fmaxf(m, fmaxf(fmaxf(v.x, v.y), fmaxf(v.z, v.w)));
    }
    g_kr[((size_t)b * CDIM + c) * RREG + r] = m;
}

// ---------------- K4: routing + top-32 ----------------
__global__ void k_route() {
    int b = blockIdx.x, tid = threadIdx.x;
    __shared__ float qs[CDIM];
    __shared__ float part[256];
    __shared__ float a[RREG];
    for (int c = tid; c < CDIM; c += 256) qs[c] = g_q[b * CDIM + c];
    __syncthreads();
    int r = tid & 63, seg = tid >> 6;
    float s = 0.f;
    int c0 = seg * 192;
    for (int c = c0; c < c0 + 192; c++)
        s += qs[c] * g_kr[((size_t)b * CDIM + c) * RREG + r];
    part[tid] = s;
    __syncthreads();
    if (tid < RREG) a[tid] = part[tid] + part[tid + 64] + part[tid + 128] + part[tid + 192];
    __syncthreads();
    if (tid < RREG) {
        float my = a[tid];
        int rank = 0;
        #pragma unroll 8
        for (int r2 = 0; r2 < RREG; r2++) {
            float v = a[r2];
            rank += (v > my) || (v == my && r2 < tid);
        }
        if (rank < TOPKN) g_sel[b * TOPKN + rank] = tid;
    }
}

// ---------------- K5: gathered attention ----------------
__global__ __launch_bounds__(128) void k_attn() {
    int b = blockIdx.x, h = blockIdx.y;
    int tid = threadIdx.x;
    __shared__ float qsh[HD];
    __shared__ float kt[HD * 17];
    __shared__ float vt[HD * 17];
    __shared__ float lg[SREG];
    __shared__ float pr[SREG];
    __shared__ float s_alpha, s_l, s_m;

    const float SCALE = 0.036084391824351615f;
    int ch0 = h * HD;
    if (tid < HD) qsh[tid] = g_q[b * CDIM + ch0 + tid];
    if (tid == 0) { s_m = -1e30f; s_l = 0.f; s_alpha = 0.f; }
    float o_d = 0.f;
    __syncthreads();

    size_t kvb = (size_t)b * TWOC * HW;
    int d  = tid >> 1;
    int p0 = (tid & 1) * 2;

    for (int i = 0; i < TOPKN; i++) {
        int reg = g_sel[b * TOPKN + i];
        int pbase = ((reg >> 3) * 4) * 32 + (reg & 7) * 4;
        {
            const float* sk = &g_kv[kvb + (size_t)(ch0 + d) * HW + pbase];
            float4 v0 = *(const float4*)&sk[p0 * 32];
            float4 v1 = *(const float4*)&sk[(p0 + 1) * 32];
            float* dk = &kt[d * 17 + p0 * 4];
            dk[0] = v0.x; dk[1] = v0.y; dk[2] = v0.z; dk[3] = v0.w;
            dk[4] = v1.x; dk[5] = v1.y; dk[6] = v1.z; dk[7] = v1.w;
            const float* sv = &g_kv[kvb + (size_t)(CDIM + ch0 + d) * HW + pbase];
            float4 u0 = *(const float4*)&sv[p0 * 32];
            float4 u1 = *(const float4*)&sv[(p0 + 1) * 32];
            float* dv = &vt[d * 17 + p0 * 4];
            dv[0] = u0.x; dv[1] = u0.y; dv[2] = u0.z; dv[3] = u0.w;
            dv[4] = u1.x; dv[5] = u1.y; dv[6] = u1.z; dv[7] = u1.w;
        }
        __syncthreads();
        if (tid < SREG) {
            float s = 0.f;
            #pragma unroll 16
            for (int dd = 0; dd < HD; dd++) s += qsh[dd] * kt[dd * 17 + tid];
            lg[tid] = s * SCALE;
        }
        __syncthreads();
        if (tid == 0) {
            float nm = s_m;
            #pragma unroll
            for (int s2 = 0; s2 < SREG; s2++) nm = fmaxf(nm, lg[s2]);
            float al = expf(s_m - nm);
            float su = 0.f;
            #pragma unroll
            for (int s2 = 0; s2 < SREG; s2++) { float p = expf(lg[s2] - nm); pr[s2] = p; su += p; }
            s_l = s_l * al + su;
            s_m = nm;
            s_alpha = al;
        }
        __syncthreads();
        if (tid < HD) {
            float acc = 0.f;
            #pragma unroll
            for (int s2 = 0; s2 < SREG; s2++) acc += pr[s2] * vt[tid * 17 + s2];
            o_d = o_d * s_alpha + acc;
        }
        __syncthreads();
    }
    if (tid < HD) g_o[b * CDIM + ch0 + tid] = o_d / s_l;
}

// ---------------- K6: output projection ----------------
__global__ void k_outproj(float* __restrict__ out, const float* __restrict__ Wo,
                          const float* __restrict__ bo, int out_cols, int bo_n) {
    int b = blockIdx.x;
    __shared__ float osh[CDIM];
    int tid = threadIdx.x;
    for (int c = tid; c < CDIM; c += 256) osh[c] = g_o[b * CDIM + c];
    __syncthreads();
    int w = tid >> 5, lane = tid & 31;
    int j = blockIdx.y * 8 + w;
    if (j >= out_cols) return;
    float s = 0.f;
    const float* wr = Wo + (size_t)j * CDIM;
    for (int c = lane; c < CDIM; c += 32) s += osh[c] * wr[c];
    #pragma unroll
    for (int off = 16; off; off >>= 1) s += __shfl_down_sync(0xffffffffu, s, off);
    if (lane == 0) out[(size_t)b * out_cols + j] = s + (j < bo_n ? bo[j] : 0.f);
}

// ---------------- host ----------------
extern "C" void kernel_launch(void* const* d_in, const int* in_sizes, int n_in,
                              void* d_out, int out_size) {
    const float* x   = (const float*)d_in[0];
    const float* Wq  = (const float*)d_in[1];
    const float* bq  = (const float*)d_in[2];
    const float* Wkv = (const float*)d_in[3];
    const float* bkv = (const float*)d_in[4];
    const float* Wo  = (const float*)d_in[5];
    const float* bo  = (const float*)d_in[6];
    float* out = (float*)d_out;

    int B = in_sizes[0] / (NTOK * CDIM);
    int out_cols = out_size / B;
    int bo_n = (n_in > 6) ? in_sizes[6] : 0;

    cudaFuncSetAttribute(k_gemm_mma, cudaFuncAttributeMaxDynamicSharedMemorySize, GEMM_SMEM);

    k_convA   <<<(TWOC * CDIM + 255) / 256, 256>>>(Wkv);
    k_convB   <<<dim3(HW / 32, CDIM / 32, B), dim3(32, 8)>>>(x);
    k_qproj   <<<dim3(B, CDIM / 8), 256>>>(x, Wq, bq);
    k_gemm_mma<<<dim3(TWOC / 128, NTOT / 128), 256, GEMM_SMEM>>>(bkv);
    k_pool    <<<dim3(B, (CDIM * RREG) / 256), 256>>>();
    k_route   <<<dim3(B), 256>>>();
    k_attn    <<<dim3(B, NHEAD), 128>>>();
    k_outproj <<<dim3(B, (out_cols + 7) / 8), 256>>>(out, Wo, bo, out_cols, bo_n);
}

// round 4
// speedup vs baseline: 3.4134x; 1.6758x over previous
#include <cuda_runtime.h>
#include <cuda_bf16.h>
#include <cuda_fp16.h>
#include <math.h>
#include <stdint.h>

// Problem constants
#define BATCH 64
#define CDIM  768
#define TWOC  1536
#define NTOK  1025
#define HW    1024
#define RREG  64
#define SREG  16
#define NHEAD 12
#define HD    64
#define TOPKN 32

#define NTOT   (BATCH * HW)       // 65536 merged N
#define NCHUNK 24                 // 768 / 32
#define STAGE_K 32768             // K-GEMM: 4 tiles x 8KB
#define SMEM_K  (3 * STAGE_K)     // 96KB
#define STAGE_V 16384             // V-GEMM: 2 tiles x 8KB
#define SMEM_V  (3 * STAGE_V)     // 48KB
#define NSEL   (TOPKN * SREG)     // 512 selected positions / batch

// ---------------- scratch ----------------
static __device__ float g_k [(size_t)BATCH * CDIM * HW];      // K full, fp32
static __device__ float g_vc[(size_t)BATCH * CDIM * NSEL];    // V compact
static __device__ float g_q [BATCH * CDIM];
static __device__ float g_kr[(size_t)BATCH * CDIM * RREG];
static __device__ int   g_sel[BATCH * TOPKN];
static __device__ int   g_nidx[BATCH * NSEL];
static __device__ float g_o [BATCH * CDIM];
static __device__ __align__(128) __nv_bfloat16 g_Ahi[CDIM * CDIM];          // Wk hi
static __device__ __align__(128) __nv_bfloat16 g_Alo[CDIM * CDIM];          // Wk lo
static __device__ __align__(128) __half        g_Af16[CDIM * CDIM];         // Wv fp16
static __device__ __align__(128) __nv_bfloat16 g_Bthi[(size_t)NTOT * CDIM];
static __device__ __align__(128) __nv_bfloat16 g_Btlo[(size_t)NTOT * CDIM];
static __device__ __align__(128) __half        g_Bf16[(size_t)NTOT * CDIM];

// ---------------- PTX helpers ----------------
__device__ __forceinline__ uint32_t smem_u32(const void* p) {
    uint32_t a;
    asm("{ .reg .u64 t; cvta.to.shared.u64 t, %1; cvt.u32.u64 %0, t; }" : "=r"(a) : "l"(p));
    return a;
}
__device__ __forceinline__ void cp16(uint32_t dst, const void* src) {
    asm volatile("cp.async.cg.shared.global [%0], [%1], 16;" :: "r"(dst), "l"(src));
}
__device__ __forceinline__ void cp_commit() { asm volatile("cp.async.commit_group;"); }
__device__ __forceinline__ void cp_wait1()  { asm volatile("cp.async.wait_group 1;"); }
__device__ __forceinline__ void ldsm4(uint32_t* r, uint32_t a) {
    asm volatile("ldmatrix.sync.aligned.m8n8.x4.shared.b16 {%0,%1,%2,%3}, [%4];"
        : "=r"(r[0]), "=r"(r[1]), "=r"(r[2]), "=r"(r[3]) : "r"(a));
}
__device__ __forceinline__ void mma_bf16(float* d, const uint32_t* a, const uint32_t* b) {
    asm volatile("mma.sync.aligned.m16n8k16.row.col.f32.bf16.bf16.f32 "
        "{%0,%1,%2,%3}, {%4,%5,%6,%7}, {%8,%9}, {%0,%1,%2,%3};"
        : "+f"(d[0]), "+f"(d[1]), "+f"(d[2]), "+f"(d[3])
        : "r"(a[0]), "r"(a[1]), "r"(a[2]), "r"(a[3]), "r"(b[0]), "r"(b[1]));
}
__device__ __forceinline__ void mma_f16(float* d, const uint32_t* a, const uint32_t* b) {
    asm volatile("mma.sync.aligned.m16n8k16.row.col.f32.f16.f16.f32 "
        "{%0,%1,%2,%3}, {%4,%5,%6,%7}, {%8,%9}, {%0,%1,%2,%3};"
        : "+f"(d[0]), "+f"(d[1]), "+f"(d[2]), "+f"(d[3])
        : "r"(a[0]), "r"(a[1]), "r"(a[2]), "r"(a[3]), "r"(b[0]), "r"(b[1]));
}

// ---------------- K0a: split Wkv: K-half -> bf16 hi/lo, V-half -> fp16 -----
__global__ void k_convA(const float* __restrict__ Wkv) {
    int i = blockIdx.x * 256 + threadIdx.x;
    if (i < CDIM * CDIM) {
        float wk = Wkv[i];
        __nv_bfloat16 h = __float2bfloat16(wk);
        g_Ahi[i] = h;
        g_Alo[i] = __float2bfloat16(wk - __bfloat162float(h));
        g_Af16[i] = __float2half(Wkv[CDIM * CDIM + i]);
    }
}

// ---------------- K0b: transpose x_spa -> Bt[n,k]: bf16 hi/lo + fp16 -------
__global__ void k_convB(const float* __restrict__ x) {
    __shared__ float t[32][33];
    int b  = blockIdx.z;
    int n0 = blockIdx.x * 32;
    int k0 = blockIdx.y * 32;
    const float* src = x + (size_t)b * NTOK * CDIM + CDIM;
    int tx = threadIdx.x, ty = threadIdx.y;
    #pragma unroll
    for (int i = ty; i < 32; i += 8)
        t[i][tx] = src[(size_t)(k0 + i) * HW + n0 + tx];
    __syncthreads();
    #pragma unroll
    for (int i = ty; i < 32; i += 8) {
        float w = t[tx][i];
        __nv_bfloat16 h = __float2bfloat16(w);
        size_t idx = ((size_t)b * HW + n0 + i) * CDIM + k0 + tx;
        g_Bthi[idx] = h;
        g_Btlo[idx] = __float2bfloat16(w - __bfloat162float(h));
        g_Bf16[idx] = __float2half(w);
    }
}

// ---------------- K1: q projection ----------------
__global__ void k_qproj(const float* __restrict__ x, const float* __restrict__ Wq,
                        const float* __restrict__ bq) {
    int b = blockIdx.x;
    __shared__ float xs[CDIM];
    int tid = threadIdx.x;
    for (int c = tid; c < CDIM; c += 256) xs[c] = x[(size_t)b * NTOK * CDIM + c];
    __syncthreads();
    int w = tid >> 5, lane = tid & 31;
    int j = blockIdx.y * 8 + w;
    float s = 0.f;
    const float* wr = Wq + (size_t)j * CDIM;
    for (int c = lane; c < CDIM; c += 32) s += xs[c] * wr[c];
    #pragma unroll
    for (int off = 16; off; off >>= 1) s += __shfl_down_sync(0xffffffffu, s, off);
    if (lane == 0) g_q[b * CDIM + j] = s + bq[j];
}

// ---------------- K2: K-GEMM, 3-term split bf16 ----------------
// K[768,65536] = Wk @ X. CTA 128x128, 8 warps 64x32, 3-stage cp.async.
__global__ void __launch_bounds__(256, 2) k_gemm_k(const float* __restrict__ bkv) {
    extern __shared__ __align__(1024) char smem[];
    uint32_t sb = smem_u32(smem);
    int tid = threadIdx.x;
    int m0 = blockIdx.x * 128;            // 6 m-tiles (fast -> B reuse)
    int n0 = blockIdx.y * 128;            // 512 n-tiles

    auto load_stage = [&](uint32_t st, int kc) {
        #pragma unroll
        for (int rep = 0; rep < 2; rep++) {
            int q    = tid + rep * 256;
            int row  = q >> 2, quad = q & 3;
            uint32_t doff = row * 64 + ((quad ^ ((row >> 1) & 3)) << 4);
            size_t aoff = (size_t)(m0 + row) * CDIM + kc + quad * 8;
            size_t boff = (size_t)(n0 + row) * CDIM + kc + quad * 8;
            cp16(st +         doff, g_Ahi  + aoff);
            cp16(st +  8192 + doff, g_Alo  + aoff);
            cp16(st + 16384 + doff, g_Bthi + boff);
            cp16(st + 24576 + doff, g_Btlo + boff);
        }
        cp_commit();
    };

    load_stage(sb, 0);
    load_stage(sb + STAGE_K, 32);

    int lane = tid & 31, wid = tid >> 5;
    int wm = wid >> 2, wn = wid & 3;
    uint32_t a_base = (uint32_t)((wm * 64 + (lane & 15)) * 64);
    uint32_t swa    = ((lane & 15) >> 1) & 3;
    uint32_t akh    = lane >> 4;
    uint32_t b_row  = (uint32_t)(wn * 32 + ((lane >> 4) << 3) + (lane & 7));
    uint32_t b_base = b_row * 64;
    uint32_t swb    = ((((lane >> 4) << 3) + (lane & 7)) >> 1) & 3;
    uint32_t bkh    = (lane >> 3) & 1;

    float acc[4][4][4] = {};

    for (int c = 0; c < NCHUNK; c++) {
        cp_wait1();
        __syncthreads();
        if (c + 2 < NCHUNK) load_stage(sb + ((c + 2) % 3) * STAGE_K, (c + 2) * 32);
        uint32_t st = sb + (c % 3) * STAGE_K;
        #pragma unroll
        for (int ks = 0; ks < 2; ks++) {
            uint32_t qk = ks * 2;
            uint32_t aoff = a_base + (((qk + akh) ^ swa) << 4);
            uint32_t boff = b_base + (((qk + bkh) ^ swb) << 4);
            uint32_t ah[4][4], al[4][4], bb[4][2];
            ldsm4(&bb[0][0], st + 16384 + boff);
            ldsm4(&bb[2][0], st + 16384 + boff + 1024);
            #pragma unroll
            for (int mt = 0; mt < 4; mt++) ldsm4(ah[mt], st + mt * 1024 + aoff);
            #pragma unroll
            for (int mt = 0; mt < 4; mt++)
                #pragma unroll
                for (int nt = 0; nt < 4; nt++) mma_bf16(acc[mt][nt], ah[mt], bb[nt]);
            #pragma unroll
            for (int mt = 0; mt < 4; mt++) ldsm4(al[mt], st + 8192 + mt * 1024 + aoff);
            #pragma unroll
            for (int mt = 0; mt < 4; mt++)
                #pragma unroll
                for (int nt = 0; nt < 4; nt++) mma_bf16(acc[mt][nt], al[mt], bb[nt]);
            ldsm4(&bb[0][0], st + 24576 + boff);
            ldsm4(&bb[2][0], st + 24576 + boff + 1024);
            #pragma unroll
            for (int mt = 0; mt < 4; mt++)
                #pragma unroll
                for (int nt = 0; nt < 4; nt++) mma_bf16(acc[mt][nt], ah[mt], bb[nt]);
        }
    }

    int b    = n0 >> 10;
    int pos0 = (n0 & 1023) + wn * 32;
    #pragma unroll
    for (int mt = 0; mt < 4; mt++) {
        int row = m0 + wm * 64 + mt * 16 + (lane >> 2);
        float bias0 = bkv[row], bias8 = bkv[row + 8];
        float* base0 = &g_k[((size_t)b * CDIM + row) * HW + pos0];
        float* base8 = base0 + (size_t)8 * HW;
        #pragma unroll
        for (int nt = 0; nt < 4; nt++) {
            int col = nt * 8 + (lane & 3) * 2;
            *(float2*)&base0[col] = make_float2(acc[mt][nt][0] + bias0, acc[mt][nt][1] + bias0);
            *(float2*)&base8[col] = make_float2(acc[mt][nt][2] + bias8, acc[mt][nt][3] + bias8);
        }
    }
}

// ---------------- K3: region max-pool (on K) ----------------
__global__ void k_pool() {
    int b   = blockIdx.x;
    int lin = blockIdx.y * 256 + threadIdx.x;
    int c = lin >> 6, r = lin & 63;
    int h0 = (r >> 3) * 4, w0 = (r & 7) * 4;
    const float* base = &g_k[((size_t)b * CDIM + c) * HW + h0 * 32 + w0];
    float m = -1e30f;
    #pragma unroll
    for (int dh = 0; dh < 4; dh++) {
        float4 v = *(const float4*)&base[dh * 32];
        m = fmaxf(m, fmaxf(fmaxf(v.x, v.y), fmaxf(v.z, v.w)));
    }
    g_kr[((size_t)b * CDIM + c) * RREG + r] = m;
}

// ---------------- K4: routing + top-32 ----------------
__global__ void k_route() {
    int b = blockIdx.x, tid = threadIdx.x;
    __shared__ float qs[CDIM];
    __shared__ float part[256];
    __shared__ float a[RREG];
    for (int c = tid; c < CDIM; c += 256) qs[c] = g_q[b * CDIM + c];
    __syncthreads();
    int r = tid & 63, seg = tid >> 6;
    float s = 0.f;
    int c0 = seg * 192;
    for (int c = c0; c < c0 + 192; c++)
        s += qs[c] * g_kr[((size_t)b * CDIM + c) * RREG + r];
    part[tid] = s;
    __syncthreads();
    if (tid < RREG) a[tid] = part[tid] + part[tid + 64] + part[tid + 128] + part[tid + 192];
    __syncthreads();
    if (tid < RREG) {
        float my = a[tid];
        int rank = 0;
        #pragma unroll 8
        for (int r2 = 0; r2 < RREG; r2++) {
            float v = a[r2];
            rank += (v > my) || (v == my && r2 < tid);
        }
        if (rank < TOPKN) g_sel[b * TOPKN + rank] = tid;
    }
}

// ---------------- K4b: build selected-position index list ----------------
__global__ void k_selpos() {
    int b = blockIdx.x, j = threadIdx.x;   // 512 threads
    int rank = j >> 4, s = j & 15;
    int reg = g_sel[b * TOPKN + rank];
    int n = ((reg >> 3) * 4 + (s >> 2)) * 32 + (reg & 7) * 4 + (s & 3);
    g_nidx[b * NSEL + j] = b * HW + n;     // global Bt row index
}

// ---------------- K5: V-GEMM, fp16 single-pass, selected columns only ------
// Vc[768, 512/batch] = Wv @ X[:, sel]. CTA 128x128, 3-stage.
__global__ void __launch_bounds__(256, 2) k_gemm_v(const float* __restrict__ bkv) {
    extern __shared__ __align__(1024) char smem[];
    uint32_t sb = smem_u32(smem);
    __shared__ int nidx_s[128];
    int tid = threadIdx.x;
    int m0 = blockIdx.x * 128;            // 6 m-tiles
    int ntile = blockIdx.y;               // 256: b = ntile>>2, j0 = (ntile&3)*128
    int b  = ntile >> 2;
    int j0 = (ntile & 3) * 128;

    if (tid < 128) nidx_s[tid] = g_nidx[b * NSEL + j0 + tid];
    __syncthreads();

    auto load_stage = [&](uint32_t st, int kc) {
        #pragma unroll
        for (int rep = 0; rep < 2; rep++) {
            int q    = tid + rep * 256;
            int row  = q >> 2, quad = q & 3;
            uint32_t doff = row * 64 + ((quad ^ ((row >> 1) & 3)) << 4);
            cp16(st +        doff, g_Af16 + (size_t)(m0 + row) * CDIM + kc + quad * 8);
            cp16(st + 8192 + doff, g_Bf16 + (size_t)nidx_s[row] * CDIM + kc + quad * 8);
        }
        cp_commit();
    };

    load_stage(sb, 0);
    load_stage(sb + STAGE_V, 32);

    int lane = tid & 31, wid = tid >> 5;
    int wm = wid >> 2, wn = wid & 3;
    uint32_t a_base = (uint32_t)((wm * 64 + (lane & 15)) * 64);
    uint32_t swa    = ((lane & 15) >> 1) & 3;
    uint32_t akh    = lane >> 4;
    uint32_t b_row  = (uint32_t)(wn * 32 + ((lane >> 4) << 3) + (lane & 7));
    uint32_t b_base = b_row * 64;
    uint32_t swb    = ((((lane >> 4) << 3) + (lane & 7)) >> 1) & 3;
    uint32_t bkh    = (lane >> 3) & 1;

    float acc[4][4][4] = {};

    for (int c = 0; c < NCHUNK; c++) {
        cp_wait1();
        __syncthreads();
        if (c + 2 < NCHUNK) load_stage(sb + ((c + 2) % 3) * STAGE_V, (c + 2) * 32);
        uint32_t st = sb + (c % 3) * STAGE_V;
        #pragma unroll
        for (int ks = 0; ks < 2; ks++) {
            uint32_t qk = ks * 2;
            uint32_t aoff = a_base + (((qk + akh) ^ swa) << 4);
            uint32_t boff = b_base + (((qk + bkh) ^ swb) << 4);
            uint32_t ah[4][4], bb[4][2];
            ldsm4(&bb[0][0], st + 8192 + boff);
            ldsm4(&bb[2][0], st + 8192 + boff + 1024);
            #pragma unroll
            for (int mt = 0; mt < 4; mt++) ldsm4(ah[mt], st + mt * 1024 + aoff);
            #pragma unroll
            for (int mt = 0; mt < 4; mt++)
                #pragma unroll
                for (int nt = 0; nt < 4; nt++) mma_f16(acc[mt][nt], ah[mt], bb[nt]);
        }
    }

    #pragma unroll
    for (int mt = 0; mt < 4; mt++) {
        int row = m0 + wm * 64 + mt * 16 + (lane >> 2);
        float bias0 = bkv[CDIM + row], bias8 = bkv[CDIM + row + 8];
        float* base0 = &g_vc[((size_t)b * CDIM + row) * NSEL + j0 + wn * 32];
        float* base8 = base0 + (size_t)8 * NSEL;
        #pragma unroll
        for (int nt = 0; nt < 4; nt++) {
            int col = nt * 8 + (lane & 3) * 2;
            *(float2*)&base0[col] = make_float2(acc[mt][nt][0] + bias0, acc[mt][nt][1] + bias0);
            *(float2*)&base8[col] = make_float2(acc[mt][nt][2] + bias8, acc[mt][nt][3] + bias8);
        }
    }
}

// ---------------- K6: gathered attention (K from g_k, V compact) -----------
__global__ __launch_bounds__(128) void k_attn() {
    int b = blockIdx.x, h = blockIdx.y;
    int tid = threadIdx.x;
    __shared__ float qsh[HD];
    __shared__ float kt[HD * 17];
    __shared__ float vt[HD * 17];
    __shared__ float lg[SREG];
    __shared__ float pr[SREG];
    __shared__ float s_alpha, s_l, s_m;

    const float SCALE = 0.036084391824351615f;
    int ch0 = h * HD;
    if (tid < HD) qsh[tid] = g_q[b * CDIM + ch0 + tid];
    if (tid == 0) { s_m = -1e30f; s_l = 0.f; s_alpha = 0.f; }
    float o_d = 0.f;
    __syncthreads();

    size_t kb = (size_t)b * CDIM * HW;
    int d  = tid >> 1;
    int p0 = (tid & 1) * 2;

    for (int i = 0; i < TOPKN; i++) {
        int reg = g_sel[b * TOPKN + i];
        int pbase = ((reg >> 3) * 4) * 32 + (reg & 7) * 4;
        {
            const float* sk = &g_k[kb + (size_t)(ch0 + d) * HW + pbase];
            float4 v0 = *(const float4*)&sk[p0 * 32];
            float4 v1 = *(const float4*)&sk[(p0 + 1) * 32];
            float* dk = &kt[d * 17 + p0 * 4];
            dk[0] = v0.x; dk[1] = v0.y; dk[2] = v0.z; dk[3] = v0.w;
            dk[4] = v1.x; dk[5] = v1.y; dk[6] = v1.z; dk[7] = v1.w;
            const float* sv = &g_vc[((size_t)b * CDIM + ch0 + d) * NSEL + i * SREG + p0 * 4];
            float4 u0 = *(const float4*)&sv[0];
            float4 u1 = *(const float4*)&sv[4];
            float* dv = &vt[d * 17 + p0 * 4];
            dv[0] = u0.x; dv[1] = u0.y; dv[2] = u0.z; dv[3] = u0.w;
            dv[4] = u1.x; dv[5] = u1.y; dv[6] = u1.z; dv[7] = u1.w;
        }
        __syncthreads();
        if (tid < SREG) {
            float s = 0.f;
            #pragma unroll 16
            for (int dd = 0; dd < HD; dd++) s += qsh[dd] * kt[dd * 17 + tid];
            lg[tid] = s * SCALE;
        }
        __syncthreads();
        if (tid == 0) {
            float nm = s_m;
            #pragma unroll
            for (int s2 = 0; s2 < SREG; s2++) nm = fmaxf(nm, lg[s2]);
            float al = expf(s_m - nm);
            float su = 0.f;
            #pragma unroll
            for (int s2 = 0; s2 < SREG; s2++) { float p = expf(lg[s2] - nm); pr[s2] = p; su += p; }
            s_l = s_l * al + su;
            s_m = nm;
            s_alpha = al;
        }
        __syncthreads();
        if (tid < HD) {
            float acc = 0.f;
            #pragma unroll
            for (int s2 = 0; s2 < SREG; s2++) acc += pr[s2] * vt[tid * 17 + s2];
            o_d = o_d * s_alpha + acc;
        }
        __syncthreads();
    }
    if (tid < HD) g_o[b * CDIM + ch0 + tid] = o_d / s_l;
}

// ---------------- K7: output projection ----------------
__global__ void k_outproj(float* __restrict__ out, const float* __restrict__ Wo,
                          const float* __restrict__ bo, int out_cols, int bo_n) {
    int b = blockIdx.x;
    __shared__ float osh[CDIM];
    int tid = threadIdx.x;
    for (int c = tid; c < CDIM; c += 256) osh[c] = g_o[b * CDIM + c];
    __syncthreads();
    int w = tid >> 5, lane = tid & 31;
    int j = blockIdx.y * 8 + w;
    if (j >= out_cols) return;
    float s = 0.f;
    const float* wr = Wo + (size_t)j * CDIM;
    for (int c = lane; c < CDIM; c += 32) s += osh[c] * wr[c];
    #pragma unroll
    for (int off = 16; off; off >>= 1) s += __shfl_down_sync(0xffffffffu, s, off);
    if (lane == 0) out[(size_t)b * out_cols + j] = s + (j < bo_n ? bo[j] : 0.f);
}

// ---------------- host ----------------
extern "C" void kernel_launch(void* const* d_in, const int* in_sizes, int n_in,
                              void* d_out, int out_size) {
    const float* x   = (const float*)d_in[0];
    const float* Wq  = (const float*)d_in[1];
    const float* bq  = (const float*)d_in[2];
    const float* Wkv = (const float*)d_in[3];
    const float* bkv = (const float*)d_in[4];
    const float* Wo  = (const float*)d_in[5];
    const float* bo  = (const float*)d_in[6];
    float* out = (float*)d_out;

    int B = in_sizes[0] / (NTOK * CDIM);
    int out_cols = out_size / B;
    int bo_n = (n_in > 6) ? in_sizes[6] : 0;

    cudaFuncSetAttribute(k_gemm_k, cudaFuncAttributeMaxDynamicSharedMemorySize, SMEM_K);
    cudaFuncSetAttribute(k_gemm_v, cudaFuncAttributeMaxDynamicSharedMemorySize, SMEM_V);

    k_convA  <<<(CDIM * CDIM + 255) / 256, 256>>>(Wkv);
    k_convB  <<<dim3(HW / 32, CDIM / 32, B), dim3(32, 8)>>>(x);
    k_qproj  <<<dim3(B, CDIM / 8), 256>>>(x, Wq, bq);
    k_gemm_k <<<dim3(CDIM / 128, NTOT / 128), 256, SMEM_K>>>(bkv);
    k_pool   <<<dim3(B, (CDIM * RREG) / 256), 256>>>();
    k_route  <<<dim3(B), 256>>>();
    k_selpos <<<B, NSEL>>>();
    k_gemm_v <<<dim3(CDIM / 128, (B * NSEL) / 128), 256, SMEM_V>>>(bkv);
    k_attn   <<<dim3(B, NHEAD), 128>>>();
    k_outproj<<<dim3(B, (out_cols + 7) / 8), 256>>>(out, Wo, bo, out_cols, bo_n);
}